// round 12
// baseline (speedup 1.0000x reference)
#include <cuda_runtime.h>
#include <cstdint>

// BidPrefix: row = [rates[0..299], market_price, bid]
//   cp1[j] = prod_{k<j} rates[k]
//   out[0:B]  = cp1[bid]            (bid in [0,300])
//   out[B:2B] = cp1[mp] - cp1[mp+1] (mp  in [0,299])
//
// Block-staged meta + cp.async double-buffered ring.
//  S1: warp0 gathers the block's 32 row tails -> smem (kills tail->load dep).
//  S2: each warp streams its 16 rows through a depth-2 smem ring: iter j
//      issues row j+1's five 8B cp.asyncs (per-lane src_size = pred ? 8 : 0,
//      zero-fill) + commit_group, then cp.async.wait_group 1 -> row j ready.
//      Loads get a full row-period of latency cover at ~zero register cost.
//      Zero-filled chunks are safe: queries only reference indices <= maxelem
//      (selects take the 1.0 branch elsewhere), unselected chain terms unused.
//  S3: results staged in smem, 32-wide coalesced stores.
// Interleaved ownership: lane t owns float2 chunks #(t+32k), k=0..4 (it both
// issues and consumes them -> wait_group alone orders the smem traffic).
// cp1[x], x = 64q + r (warp-uniform):
//   m_t = c_q[t] * (2t<r ? vx_q : 1) * (2t+1<r ? vy_q : 1); butterfly-product.

static constexpr int ROW     = 302;
static constexpr int ROWF2   = 151;
static constexpr int RPB     = 32;             // rows per block
static constexpr int RPW     = 16;             // rows per warp
static constexpr int THREADS = 64;             // 2 warps
static constexpr int CHUNKS  = 160;            // 5*32 float2 slots per row buf
static constexpr unsigned FULL = 0xffffffffu;

__device__ __forceinline__ void cpa8(uint32_t dst, const float2* src, uint32_t sz) {
    asm volatile("cp.async.ca.shared.global [%0], [%1], 8, %2;"
                 :: "r"(dst), "l"(src), "r"(sz) : "memory");
}
__device__ __forceinline__ void cpa_commit() {
    asm volatile("cp.async.commit_group;" ::: "memory");
}
__device__ __forceinline__ void cpa_wait1() {
    asm volatile("cp.async.wait_group 1;" ::: "memory");
}

struct QPre { float m, vx, vy; };

__device__ __forceinline__ QPre qpre(int x, int lane2,
                                     const float2& v0, const float2& v1,
                                     const float2& v2, const float2& v3,
                                     const float2& v4,
                                     float c1, float c2, float c3, float c4)
{
    const int q = x >> 6, r = x & 63;          // warp-uniform
    float cq = 1.0f;
    cq = (q == 1) ? c1 : cq;
    cq = (q == 2) ? c2 : cq;
    cq = (q == 3) ? c3 : cq;
    cq = (q == 4) ? c4 : cq;
    float vx = v0.x, vy = v0.y;
    vx = (q == 1) ? v1.x : vx;  vy = (q == 1) ? v1.y : vy;
    vx = (q == 2) ? v2.x : vx;  vy = (q == 2) ? v2.y : vy;
    vx = (q == 3) ? v3.x : vx;  vy = (q == 3) ? v3.y : vy;
    vx = (q == 4) ? v4.x : vx;  vy = (q == 4) ? v4.y : vy;
    float m = cq;
    m *= (lane2     < r) ? vx : 1.0f;
    m *= (lane2 + 1 < r) ? vy : 1.0f;
    return {m, vx, vy};
}

__global__ __launch_bounds__(THREADS) void bidprefix_kernel(
    const float* __restrict__ in, float* __restrict__ out, int batch)
{
    __shared__ float2 meta[RPB];
    __shared__ float  rs[RPB];
    __shared__ float  rl[RPB];
    __shared__ float2 ring[2][2][CHUNKS];      // [warp][buf][chunk]

    const int tid   = threadIdx.x;
    const int lane  = tid & 31;
    const int wib   = tid >> 5;
    const int lane2 = 2 * lane;
    const int base  = blockIdx.x * RPB;

    const float2* inf2 = reinterpret_cast<const float2*>(in);

    // ---- stage 1: gather the 32 tails (MLP=32) ----
    if (tid < RPB) {
        const int r = base + tid;
        meta[tid] = (r < batch) ? inf2[(size_t)r * ROWF2 + 150]
                                : make_float2(0.f, 0.f);
    }
    __syncthreads();

    // ---- stage 2: per-warp depth-2 cp.async pipeline over 16 rows ----
    const int rbeg = RPW * wib;
    const uint32_t ring0 = (uint32_t)__cvta_generic_to_shared(&ring[wib][0][0]);

    auto issue_row = [&](int j, int buf) {     // j in [0,16]; 16 = dummy
        const bool valid = (j < RPW) && (base + rbeg + j < batch);
        float2 t = valid ? meta[rbeg + j] : make_float2(0.f, 0.f);
        const int mf = valid ? (max((int)t.y - 1, (int)t.x) >> 1) : -1;
        const int rowc = min(base + rbeg + (valid ? j : 0), batch - 1);
        const float2* G = inf2 + (size_t)rowc * ROWF2;
        const uint32_t d = ring0 + (uint32_t)buf * (CHUNKS * 8);
        #pragma unroll
        for (int k = 0; k < 5; ++k) {
            const int ch = k * 32 + lane;
            const bool p = (ch <= mf);
            cpa8(d + ch * 8, G + (p ? ch : 0), p ? 8u : 0u);  // clamped addr
        }
        cpa_commit();
    };

    issue_row(0, 0);                           // prologue

    #pragma unroll 1
    for (int j = 0; j < RPW; ++j) {
        issue_row(j + 1, (j + 1) & 1);         // next row (dummy at j=15)
        cpa_wait1();                           // row j's group complete

        const float2* S = &ring[wib][j & 1][0];
        const float2 v0 = S[lane];
        const float2 v1 = S[lane +  32];
        const float2 v2 = S[lane +  64];
        const float2 v3 = S[lane +  96];
        const float2 v4 = S[lane + 128];

        const float2 t = meta[rbeg + j];
        const int mp  = (int)t.x;              // 0..299
        const int bid = (int)t.y;              // 0..300

        const float c1 = v0.x * v0.y;
        const float c2 = c1 * (v1.x * v1.y);
        const float c3 = c2 * (v2.x * v2.y);
        const float c4 = c3 * (v3.x * v3.y);

        const QPre sb = qpre(bid, lane2, v0, v1, v2, v3, v4, c1, c2, c3, c4);
        const QPre sm = qpre(mp,  lane2, v0, v1, v2, v3, v4, c1, c2, c3, c4);

        float m1 = sb.m, m2 = sm.m;
        #pragma unroll
        for (int off = 16; off; off >>= 1) {   // 2 chains pipeline SHFL latency
            const float w1 = __shfl_xor_sync(FULL, m1, off);
            const float w2 = __shfl_xor_sync(FULL, m2, off);
            m1 *= w1;
            m2 *= w2;
        }
        // m1 = cp1[bid], m2 = cp1[mp]

        const float rsel = (mp & 1) ? sm.vy : sm.vx;
        const float rmp  = __shfl_sync(FULL, rsel, (mp & 63) >> 1);

        if (lane == 0) {
            rs[rbeg + j] = m1;
            rl[rbeg + j] = m2 - m2 * rmp;      // cp1[mp] - cp1[mp+1]
        }
    }
    __syncthreads();

    // ---- stage 3: coalesced 32-wide output stores ----
    if (tid < RPB) {
        const int r = base + tid;
        if (r < batch) {
            out[r]         = rs[tid];
            out[batch + r] = rl[tid];
        }
    }
}

extern "C" void kernel_launch(void* const* d_in, const int* in_sizes, int n_in,
                              void* d_out, int out_size)
{
    const float* in  = (const float*)d_in[0];
    float*       out = (float*)d_out;
    const int batch  = in_sizes[0] / ROW;      // 500000

    const int blocks = (batch + RPB - 1) / RPB;   // 15625
    bidprefix_kernel<<<blocks, THREADS>>>(in, out, batch);
}

// round 14
// speedup vs baseline: 1.0276x; 1.0276x over previous
#include <cuda_runtime.h>
#include <cstdint>

// BidPrefix: row = [rates[0..299], market_price, bid]
//   cp1[j] = prod_{k<j} rates[k]
//   out[0:B]  = cp1[bid]            (bid in [0,300])
//   out[B:2B] = cp1[mp] - cp1[mp+1] (mp  in [0,299])
//
// Block-staged meta + L2-prefetch pipeline (zero-register latency hiding).
//  S1: first 64 threads gather the block's 64 row tails -> smem.
//  S2: each of 4 warps processes 16 rows. mf = max(bid-1,mp)>>1 known from
//      smem for ALL rows, so while computing row j the warp issues
//      prefetch.global.L2 for row j+2's exact predicated byte range (lanes at
//      128B stride, ONE predicated instruction, no regs, no scoreboard).
//      The consuming predicated LDGs two iterations later hit L2 (~250cyc)
//      instead of DRAM (~600cyc). Traffic stays minimal.
//  S3: results staged in smem, 64-wide coalesced stores.
// Interleaved ownership: lane t holds float2 chunks #(t+32k), k=0..4.
// cp1[x], x = 64q + r (warp-uniform):
//   m_t = c_q[t] * (2t<r ? vx_q : 1) * (2t+1<r ? vy_q : 1); butterfly-product.
// Skipped (early-exit) chunks = (1,1); never referenced by any query.

static constexpr int ROW     = 302;
static constexpr int ROWF2   = 151;
static constexpr int RPB     = 64;             // rows per block
static constexpr int RPW     = 16;             // rows per warp
static constexpr int THREADS = 128;            // 4 warps
static constexpr unsigned FULL = 0xffffffffu;

struct QPre { float m, vx, vy; };

__device__ __forceinline__ QPre qpre(int x, int lane2,
                                     const float2& v0, const float2& v1,
                                     const float2& v2, const float2& v3,
                                     const float2& v4,
                                     float c1, float c2, float c3, float c4)
{
    const int q = x >> 6, r = x & 63;          // warp-uniform
    float cq = 1.0f;
    cq = (q == 1) ? c1 : cq;
    cq = (q == 2) ? c2 : cq;
    cq = (q == 3) ? c3 : cq;
    cq = (q == 4) ? c4 : cq;
    float vx = v0.x, vy = v0.y;
    vx = (q == 1) ? v1.x : vx;  vy = (q == 1) ? v1.y : vy;
    vx = (q == 2) ? v2.x : vx;  vy = (q == 2) ? v2.y : vy;
    vx = (q == 3) ? v3.x : vx;  vy = (q == 3) ? v3.y : vy;
    vx = (q == 4) ? v4.x : vx;  vy = (q == 4) ? v4.y : vy;
    float m = cq;
    m *= (lane2     < r) ? vx : 1.0f;
    m *= (lane2 + 1 < r) ? vy : 1.0f;
    return {m, vx, vy};
}

__global__ __launch_bounds__(THREADS) void bidprefix_kernel(
    const float* __restrict__ in, float* __restrict__ out, int batch)
{
    __shared__ float2 meta[RPB];               // (mp, bid) per row
    __shared__ float  rs[RPB];
    __shared__ float  rl[RPB];

    const int tid   = threadIdx.x;
    const int lane  = tid & 31;
    const int wib   = tid >> 5;                // 0..3
    const int lane2 = 2 * lane;
    const int base  = blockIdx.x * RPB;

    const float2* inf2 = reinterpret_cast<const float2*>(in);

    // ---- stage 1: gather 64 tails (2 warps, MLP=32 each) ----
    if (tid < RPB) {
        const int r = base + tid;
        meta[tid] = (r < batch) ? inf2[(size_t)r * ROWF2 + 150]
                                : make_float2(0.f, 0.f);
    }
    __syncthreads();

    const int rbeg = RPW * wib;                // this warp's rows [rbeg, rbeg+16)

    // L2 prefetch of row (in-block index rr): lanes cover the predicated byte
    // range at 128B stride; one predicated instruction, no regs, no scoreboard.
    auto prefetch_row = [&](int rr) {
        const int g = base + rr;
        if (g >= batch) return;
        const float2 t = meta[rr];
        const int mf = max((int)t.y - 1, (int)t.x) >> 1;    // last f2 chunk
        // lane L covers f2 indices [16L, 16L+16); +16 slop for base misalign
        if (lane2 * 8 <= mf + 16) {                          // lanes 0..10 max
            const char* p = reinterpret_cast<const char*>(inf2 + (size_t)g * ROWF2)
                          + lane * 128;
            asm volatile("prefetch.global.L2 [%0];" :: "l"(p));
        }
    };

    prefetch_row(rbeg);                        // prologue: rows j=0,1
    prefetch_row(rbeg + 1);

    const float2 one = make_float2(1.f, 1.f);

    #pragma unroll 1
    for (int j = 0; j < RPW; ++j) {
        const int rloc = rbeg + j;
        if (base + rloc >= batch) break;

        if (j + 2 < RPW) prefetch_row(rloc + 2);   // distance-2 prefetch

        const float2 t = meta[rloc];
        const int mp  = (int)t.x;              // 0..299
        const int bid = (int)t.y;              // 0..300
        const int mf  = max(bid - 1, mp) >> 1; // last float2 chunk needed

        const float2* P = inf2 + (size_t)(base + rloc) * ROWF2;

        // all rounds issued together, per-lane predicated (L2 hits now)
        float2 v0 = one, v1 = one, v2 = one, v3 = one, v4 = one;
        if (lane       <= mf) v0 = P[lane];
        if (lane +  32 <= mf) v1 = P[lane +  32];
        if (lane +  64 <= mf) v2 = P[lane +  64];
        if (lane +  96 <= mf) v3 = P[lane +  96];
        if (lane + 128 <= mf) v4 = P[lane + 128];

        // vertical chain: c_j = prod over rounds < j of (vx*vy)
        const float c1 = v0.x * v0.y;
        const float c2 = c1 * (v1.x * v1.y);
        const float c3 = c2 * (v2.x * v2.y);
        const float c4 = c3 * (v3.x * v3.y);

        const QPre sb = qpre(bid, lane2, v0, v1, v2, v3, v4, c1, c2, c3, c4);
        const QPre sm = qpre(mp,  lane2, v0, v1, v2, v3, v4, c1, c2, c3, c4);

        float m1 = sb.m, m2 = sm.m;
        #pragma unroll
        for (int off = 16; off; off >>= 1) {   // 2 chains pipeline SHFL latency
            const float w1 = __shfl_xor_sync(FULL, m1, off);
            const float w2 = __shfl_xor_sync(FULL, m2, off);
            m1 *= w1;
            m2 *= w2;
        }
        // m1 = cp1[bid], m2 = cp1[mp] in every lane

        const float rsel = (mp & 1) ? sm.vy : sm.vx;
        const float rmp  = __shfl_sync(FULL, rsel, (mp & 63) >> 1);

        if (lane == 0) {
            rs[rloc] = m1;
            rl[rloc] = m2 - m2 * rmp;          // cp1[mp] - cp1[mp+1]
        }
    }
    __syncthreads();

    // ---- stage 3: coalesced 64-wide output stores ----
    if (tid < RPB) {
        const int r = base + tid;
        if (r < batch) {
            out[r]         = rs[tid];
            out[batch + r] = rl[tid];
        }
    }
}

extern "C" void kernel_launch(void* const* d_in, const int* in_sizes, int n_in,
                              void* d_out, int out_size)
{
    const float* in  = (const float*)d_in[0];
    float*       out = (float*)d_out;
    const int batch  = in_sizes[0] / ROW;      // 500000

    const int blocks = (batch + RPB - 1) / RPB;   // 7813
    bidprefix_kernel<<<blocks, THREADS>>>(in, out, batch);
}

// round 15
// speedup vs baseline: 1.0727x; 1.0439x over previous
#include <cuda_runtime.h>
#include <cstdint>

// BidPrefix: row = [rates[0..299], market_price, bid]
//   cp1[j] = prod_{k<j} rates[k]
//   out[0:B]  = cp1[bid]            (bid in [0,300])
//   out[B:2B] = cp1[mp] - cp1[mp+1] (mp  in [0,299])
//
// R14 skeleton (block-staged meta + distance-2 L2 prefetch) with the issue
// bottleneck attacked: 2 consecutive rows per iteration (amortized loop /
// prefetch overhead, 10 LDGs in flight), strength-reduced addressing (one
// per-lane pointer, all 10 loads + 4 prefetches at immediate offsets),
// mf precomputed in stage 1, 4-chain interleaved butterfly.
// Interleaved ownership: lane t holds float2 chunks #(t+32k), k=0..4.
// cp1[x], x = 64q + r (warp-uniform):
//   m_t = c_q[t] * (2t<r ? vx_q : 1) * (2t+1<r ? vy_q : 1); butterfly-product.
// Skipped (early-exit) chunks = (1,1); never referenced by any query.

static constexpr int ROW     = 302;
static constexpr int ROWF2   = 151;
static constexpr int RPB     = 32;             // rows per block
static constexpr int RPW     = 16;             // rows per warp
static constexpr int THREADS = 64;             // 2 warps
static constexpr unsigned FULL = 0xffffffffu;

struct QPre { float m, vx, vy; };

__device__ __forceinline__ QPre qpre(int x, int lane2,
                                     const float2& v0, const float2& v1,
                                     const float2& v2, const float2& v3,
                                     const float2& v4,
                                     float c1, float c2, float c3, float c4)
{
    const int q = x >> 6, r = x & 63;          // warp-uniform
    const bool e1 = (q == 1), e2 = (q == 2), e3 = (q == 3), e4 = (q == 4);
    float cq = 1.0f;
    cq = e1 ? c1 : cq;
    cq = e2 ? c2 : cq;
    cq = e3 ? c3 : cq;
    cq = e4 ? c4 : cq;
    float vx = v0.x, vy = v0.y;
    vx = e1 ? v1.x : vx;  vy = e1 ? v1.y : vy;
    vx = e2 ? v2.x : vx;  vy = e2 ? v2.y : vy;
    vx = e3 ? v3.x : vx;  vy = e3 ? v3.y : vy;
    vx = e4 ? v4.x : vx;  vy = e4 ? v4.y : vy;
    float m = cq;
    m *= (lane2     < r) ? vx : 1.0f;
    m *= (lane2 + 1 < r) ? vy : 1.0f;
    return {m, vx, vy};
}

__global__ __launch_bounds__(THREADS) void bidprefix_kernel(
    const float* __restrict__ in, float* __restrict__ out, int batch)
{
    __shared__ float2 meta[RPB];               // (mp, bid)
    __shared__ int    mfs[RPB];                // last f2 chunk needed (-1 pad)
    __shared__ float  rs[RPB];
    __shared__ float  rl[RPB];

    const int tid   = threadIdx.x;
    const int lane  = tid & 31;
    const int wib   = tid >> 5;                // 0 or 1
    const int lane2 = 2 * lane;
    const int base  = blockIdx.x * RPB;

    const float2* inf2 = reinterpret_cast<const float2*>(in);

    // ---- stage 1: gather 32 tails, precompute mf ----
    if (tid < RPB) {
        const int r = base + tid;
        if (r < batch) {
            const float2 t = inf2[(size_t)r * ROWF2 + 150];
            meta[tid] = t;
            mfs[tid]  = max((int)t.y - 1, (int)t.x) >> 1;
        } else {
            meta[tid] = make_float2(0.f, 0.f);
            mfs[tid]  = -1;
        }
    }
    __syncthreads();

    const int rbeg = RPW * wib;
    // per-lane base pointer; all loads/prefetches at immediate offsets from it
    const float2* Pl = inf2 + (size_t)(base + rbeg) * ROWF2 + lane;
    const int laneB = lane * 128;              // prefetch stride bytes

    const float2 one = make_float2(1.f, 1.f);

    #pragma unroll 1
    for (int j = 0; j < RPW; j += 2, Pl += 2 * ROWF2) {
        const int rA = rbeg + j;               // row A (in-block)
        const int rB = rA + 1;                 // row B
        if (base + rA >= batch) break;
        const bool hasB = (base + rB < batch);

        // ---- distance-2 prefetch (rows j+2, j+3), immediate-offset addrs ----
        if (j + 2 < RPW) {
            const char* pb = reinterpret_cast<const char*>(Pl - lane);
            if (laneB <= (mfs[rA + 2] << 3) + 128)
                asm volatile("prefetch.global.L2 [%0];"
                             :: "l"(pb + 2 * (ROWF2 * 8) + laneB));
            if (laneB <= (mfs[rA + 3] << 3) + 128)
                asm volatile("prefetch.global.L2 [%0];"
                             :: "l"(pb + 3 * (ROWF2 * 8) + laneB));
        }

        const int mfA = mfs[rA];
        const int mfB = hasB ? mfs[rB] : -1;

        // ---- 10 predicated LDG.64, all at [Pl + imm] ----
        float2 a0 = one, a1 = one, a2 = one, a3 = one, a4 = one;
        float2 b0 = one, b1 = one, b2 = one, b3 = one, b4 = one;
        if (lane       <= mfA) a0 = Pl[0];
        if (lane +  32 <= mfA) a1 = Pl[32];
        if (lane +  64 <= mfA) a2 = Pl[64];
        if (lane +  96 <= mfA) a3 = Pl[96];
        if (lane + 128 <= mfA) a4 = Pl[128];
        if (lane       <= mfB) b0 = Pl[ROWF2];
        if (lane +  32 <= mfB) b1 = Pl[ROWF2 +  32];
        if (lane +  64 <= mfB) b2 = Pl[ROWF2 +  64];
        if (lane +  96 <= mfB) b3 = Pl[ROWF2 +  96];
        if (lane + 128 <= mfB) b4 = Pl[ROWF2 + 128];

        // ---- chains ----
        const float cA1 = a0.x * a0.y;
        const float cA2 = cA1 * (a1.x * a1.y);
        const float cA3 = cA2 * (a2.x * a2.y);
        const float cA4 = cA3 * (a3.x * a3.y);
        const float cB1 = b0.x * b0.y;
        const float cB2 = cB1 * (b1.x * b1.y);
        const float cB3 = cB2 * (b2.x * b2.y);
        const float cB4 = cB3 * (b3.x * b3.y);

        const float2 tA = meta[rA];
        const float2 tB = meta[rB];            // garbage-safe if !hasB
        const int mpA = (int)tA.x, bidA = (int)tA.y;
        const int mpB = (int)tB.x, bidB = (int)tB.y;

        const QPre sA = qpre(bidA, lane2, a0, a1, a2, a3, a4, cA1, cA2, cA3, cA4);
        const QPre pA = qpre(mpA,  lane2, a0, a1, a2, a3, a4, cA1, cA2, cA3, cA4);
        const QPre sB = qpre(bidB, lane2, b0, b1, b2, b3, b4, cB1, cB2, cB3, cB4);
        const QPre pB = qpre(mpB,  lane2, b0, b1, b2, b3, b4, cB1, cB2, cB3, cB4);

        float m1A = sA.m, m2A = pA.m, m1B = sB.m, m2B = pB.m;
        #pragma unroll
        for (int off = 16; off; off >>= 1) {   // 4 chains pipeline SHFL latency
            const float u1 = __shfl_xor_sync(FULL, m1A, off);
            const float u2 = __shfl_xor_sync(FULL, m2A, off);
            const float u3 = __shfl_xor_sync(FULL, m1B, off);
            const float u4 = __shfl_xor_sync(FULL, m2B, off);
            m1A *= u1;  m2A *= u2;  m1B *= u3;  m2B *= u4;
        }

        // rates[mp]: reuse mp-query's selected round pair
        const float rselA = (mpA & 1) ? pA.vy : pA.vx;
        const float rselB = (mpB & 1) ? pB.vy : pB.vx;
        const float rmpA  = __shfl_sync(FULL, rselA, (mpA & 63) >> 1);
        const float rmpB  = __shfl_sync(FULL, rselB, (mpB & 63) >> 1);

        if (lane == 0) {
            rs[rA] = m1A;
            rl[rA] = m2A - m2A * rmpA;         // cp1[mp] - cp1[mp+1]
            if (hasB) {
                rs[rB] = m1B;
                rl[rB] = m2B - m2B * rmpB;
            }
        }
    }
    __syncthreads();

    // ---- stage 3: coalesced 32-wide output stores ----
    if (tid < RPB) {
        const int r = base + tid;
        if (r < batch) {
            out[r]         = rs[tid];
            out[batch + r] = rl[tid];
        }
    }
}

extern "C" void kernel_launch(void* const* d_in, const int* in_sizes, int n_in,
                              void* d_out, int out_size)
{
    const float* in  = (const float*)d_in[0];
    float*       out = (float*)d_out;
    const int batch  = in_sizes[0] / ROW;      // 500000

    const int blocks = (batch + RPB - 1) / RPB;   // 15625
    bidprefix_kernel<<<blocks, THREADS>>>(in, out, batch);
}

// round 17
// speedup vs baseline: 1.0780x; 1.0049x over previous
#include <cuda_runtime.h>
#include <cstdint>

// BidPrefix: row = [rates[0..299], market_price, bid]
//   cp1[j] = prod_{k<j} rates[k]
//   out[0:B]  = cp1[bid]            (bid in [0,300])
//   out[B:2B] = cp1[mp] - cp1[mp+1] (mp  in [0,299])
//
// Warp-private design: NO smem, NO __syncthreads, zero inter-warp coupling.
// Each warp owns 16 consecutive rows:
//  - tail pre-gather: lane L loads the tail of row row0+(L&15) (one LDG,
//    MLP=16), precomputes mp/bid/mf in registers; per-row metadata is
//    broadcast by SHFL (no LDS, no sync, no block tail effects).
//  - main loop: 2 rows/iteration, 10 predicated LDG.64 at immediate offsets
//    from one per-lane pointer, distance-2 predicated prefetch.global.L2
//    (zero-register latency hiding), 4-chain interleaved butterfly.
// Interleaved ownership: lane t holds float2 chunks #(t+32k), k=0..4.
// cp1[x], x = 64q + r (warp-uniform):
//   m_t = c_q[t] * (2t<r ? vx_q : 1) * (2t+1<r ? vy_q : 1); butterfly-product.
// Skipped (early-exit) chunks = (1,1); never referenced by any query.

static constexpr int ROW     = 302;
static constexpr int ROWF2   = 151;
static constexpr int RPW     = 16;             // rows per warp
static constexpr int WARPS   = 4;
static constexpr int THREADS = 128;
static constexpr unsigned FULL = 0xffffffffu;

struct QPre { float m, vx, vy; };

__device__ __forceinline__ QPre qpre(int x, int lane2,
                                     const float2& v0, const float2& v1,
                                     const float2& v2, const float2& v3,
                                     const float2& v4,
                                     float c1, float c2, float c3, float c4)
{
    const int q = x >> 6, r = x & 63;          // warp-uniform
    const bool e1 = (q == 1), e2 = (q == 2), e3 = (q == 3), e4 = (q == 4);
    float cq = 1.0f;
    cq = e1 ? c1 : cq;
    cq = e2 ? c2 : cq;
    cq = e3 ? c3 : cq;
    cq = e4 ? c4 : cq;
    float vx = v0.x, vy = v0.y;
    vx = e1 ? v1.x : vx;  vy = e1 ? v1.y : vy;
    vx = e2 ? v2.x : vx;  vy = e2 ? v2.y : vy;
    vx = e3 ? v3.x : vx;  vy = e3 ? v3.y : vy;
    vx = e4 ? v4.x : vx;  vy = e4 ? v4.y : vy;
    float m = cq;
    m *= (lane2     < r) ? vx : 1.0f;
    m *= (lane2 + 1 < r) ? vy : 1.0f;
    return {m, vx, vy};
}

__global__ __launch_bounds__(THREADS) void bidprefix_kernel(
    const float* __restrict__ in, float* __restrict__ out, int batch)
{
    const int lane  = threadIdx.x & 31;
    const int lane2 = 2 * lane;
    const int w     = blockIdx.x * WARPS + (threadIdx.x >> 5);
    const int row0  = w * RPW;
    if (row0 >= batch) return;

    const float2* inf2 = reinterpret_cast<const float2*>(in);

    // ---- warp-private tail pre-gather: lane L holds meta of row row0+(L&15)
    const int trow = min(row0 + (lane & 15), batch - 1);
    const float2 tl = inf2[(size_t)trow * ROWF2 + 150];
    const int mpl  = (int)tl.x;                      // 0..299
    const int bidl = (int)tl.y;                      // 0..300
    const int mfl  = max(bidl - 1, mpl) >> 1;        // last f2 chunk needed

    // per-lane base pointer; loads & prefetches at immediate offsets from it
    const float2* Pl = inf2 + (size_t)row0 * ROWF2 + lane;
    const int laneB  = lane * 128;
    const float2 one = make_float2(1.f, 1.f);

    #pragma unroll 1
    for (int j = 0; j < RPW; j += 2, Pl += 2 * ROWF2) {
        const int rA = row0 + j;
        if (rA >= batch) break;
        const bool hasB = (rA + 1 < batch);

        // broadcast per-row metadata (registers, no LDS)
        const int mpA  = __shfl_sync(FULL, mpl,  j);
        const int bidA = __shfl_sync(FULL, bidl, j);
        const int mfA  = __shfl_sync(FULL, mfl,  j);
        const int mpB  = __shfl_sync(FULL, mpl,  j + 1);
        const int bidB = __shfl_sync(FULL, bidl, j + 1);
        int mfB        = __shfl_sync(FULL, mfl,  j + 1);
        if (!hasB) mfB = -1;

        // ---- distance-2 predicated L2 prefetch (rows j+2, j+3) ----
        if (j + 2 < RPW && rA + 2 < batch) {
            const char* pb = reinterpret_cast<const char*>(Pl - lane);
            const int mf2 = __shfl_sync(FULL, mfl, j + 2);
            if (laneB <= (mf2 << 3) + 128)
                asm volatile("prefetch.global.L2 [%0];"
                             :: "l"(pb + 2 * (ROWF2 * 8) + laneB));
            if (rA + 3 < batch) {
                const int mf3 = __shfl_sync(FULL, mfl, j + 3);
                if (laneB <= (mf3 << 3) + 128)
                    asm volatile("prefetch.global.L2 [%0];"
                                 :: "l"(pb + 3 * (ROWF2 * 8) + laneB));
            }
        }

        // ---- 10 predicated LDG.64, all at [Pl + imm] ----
        float2 a0 = one, a1 = one, a2 = one, a3 = one, a4 = one;
        float2 b0 = one, b1 = one, b2 = one, b3 = one, b4 = one;
        if (lane       <= mfA) a0 = Pl[0];
        if (lane +  32 <= mfA) a1 = Pl[32];
        if (lane +  64 <= mfA) a2 = Pl[64];
        if (lane +  96 <= mfA) a3 = Pl[96];
        if (lane + 128 <= mfA) a4 = Pl[128];
        if (lane       <= mfB) b0 = Pl[ROWF2];
        if (lane +  32 <= mfB) b1 = Pl[ROWF2 +  32];
        if (lane +  64 <= mfB) b2 = Pl[ROWF2 +  64];
        if (lane +  96 <= mfB) b3 = Pl[ROWF2 +  96];
        if (lane + 128 <= mfB) b4 = Pl[ROWF2 + 128];

        // ---- chains ----
        const float cA1 = a0.x * a0.y;
        const float cA2 = cA1 * (a1.x * a1.y);
        const float cA3 = cA2 * (a2.x * a2.y);
        const float cA4 = cA3 * (a3.x * a3.y);
        const float cB1 = b0.x * b0.y;
        const float cB2 = cB1 * (b1.x * b1.y);
        const float cB3 = cB2 * (b2.x * b2.y);
        const float cB4 = cB3 * (b3.x * b3.y);

        const QPre sA = qpre(bidA, lane2, a0, a1, a2, a3, a4, cA1, cA2, cA3, cA4);
        const QPre pA = qpre(mpA,  lane2, a0, a1, a2, a3, a4, cA1, cA2, cA3, cA4);
        const QPre sB = qpre(bidB, lane2, b0, b1, b2, b3, b4, cB1, cB2, cB3, cB4);
        const QPre pB = qpre(mpB,  lane2, b0, b1, b2, b3, b4, cB1, cB2, cB3, cB4);

        float m1A = sA.m, m2A = pA.m, m1B = sB.m, m2B = pB.m;
        #pragma unroll
        for (int off = 16; off; off >>= 1) {   // 4 chains pipeline SHFL latency
            const float u1 = __shfl_xor_sync(FULL, m1A, off);
            const float u2 = __shfl_xor_sync(FULL, m2A, off);
            const float u3 = __shfl_xor_sync(FULL, m1B, off);
            const float u4 = __shfl_xor_sync(FULL, m2B, off);
            m1A *= u1;  m2A *= u2;  m1B *= u3;  m2B *= u4;
        }

        // rates[mp]: reuse mp-query's selected round pair
        const float rselA = (mpA & 1) ? pA.vy : pA.vx;
        const float rselB = (mpB & 1) ? pB.vy : pB.vx;
        const float rmpA  = __shfl_sync(FULL, rselA, (mpA & 63) >> 1);
        const float rmpB  = __shfl_sync(FULL, rselB, (mpB & 63) >> 1);

        if (lane == 0) {
            const float lastA = m2A - m2A * rmpA;   // cp1[mp] - cp1[mp+1]
            if (hasB) {                              // rA even -> aligned
                const float lastB = m2B - m2B * rmpB;
                *reinterpret_cast<float2*>(out + rA)         = make_float2(m1A, m1B);
                *reinterpret_cast<float2*>(out + batch + rA) = make_float2(lastA, lastB);
            } else {
                out[rA]         = m1A;
                out[batch + rA] = lastA;
            }
        }
    }
}

extern "C" void kernel_launch(void* const* d_in, const int* in_sizes, int n_in,
                              void* d_out, int out_size)
{
    const float* in  = (const float*)d_in[0];
    float*       out = (float*)d_out;
    const int batch  = in_sizes[0] / ROW;      // 500000

    const int warps  = (batch + RPW - 1) / RPW;        // 31250
    const int blocks = (warps + WARPS - 1) / WARPS;    // 7813
    bidprefix_kernel<<<blocks, THREADS>>>(in, out, batch);
}